// round 1
// baseline (speedup 1.0000x reference)
#include <cuda_runtime.h>
#include <cuda_bf16.h>

// Problem constants
#define BATCH   8
#define CIN     384
#define HH      56
#define WW      56
#define NPIX    3136           // 56*56
#define BP      25088          // BATCH*NPIX
#define INNER   512
#define KVOUT   1024
#define HEADS   8
#define DH      64
#define NBH     64             // BATCH*HEADS
#define SCALE_F 0.125f
#define EPS_F   1e-5f

// ---------------------------------------------------------------------------
// Scratch (device globals; no runtime allocation allowed)
// ---------------------------------------------------------------------------
__device__ float g_yq [CIN  * BP];     // dwconv+BN output, q path   [c][b*NPIX+p]
__device__ float g_ykv[CIN  * BP];     // dwconv+BN output, kv path
__device__ float g_q  [INNER * BP];    // q  = wq_pw  @ yq           [o][b*NPIX+p]
__device__ float g_kv [KVOUT * BP];    // kv = wkv_pw @ ykv  (rows 0..511 = k, 512..1023 = v)
__device__ float g_att[INNER * BP];    // attention output           [o][b*NPIX+p]
__device__ float g_diag[NBH * NPIX];
__device__ float g_ktvp[7 * NBH * DH * DH];   // partial ktv (7 n-splits)
__device__ float g_ktv [NBH * DH * DH];
__device__ float g_red[256];
__device__ float g_m0[1];

// ---------------------------------------------------------------------------
// 1) Depthwise 3x3 conv (SAME) + BN (inference), both paths in one pass
// ---------------------------------------------------------------------------
__global__ void dwconv_bn_kernel(
    const float* __restrict__ x,
    const float* __restrict__ w1, const float* __restrict__ g1, const float* __restrict__ b1,
    const float* __restrict__ m1, const float* __restrict__ v1,
    const float* __restrict__ w2, const float* __restrict__ g2, const float* __restrict__ b2,
    const float* __restrict__ m2, const float* __restrict__ v2)
{
    int idx = blockIdx.x * blockDim.x + threadIdx.x;
    if (idx >= BATCH * CIN * NPIX) return;
    int p = idx % NPIX;
    int c = (idx / NPIX) % CIN;
    int b = idx / (NPIX * CIN);
    int h = p / WW, w = p % WW;

    const float* xb = x + ((long)(b * CIN + c)) * NPIX;
    float acc1 = 0.f, acc2 = 0.f;
#pragma unroll
    for (int kh = 0; kh < 3; kh++) {
        int hh = h + kh - 1;
        if (hh < 0 || hh >= HH) continue;
#pragma unroll
        for (int kw = 0; kw < 3; kw++) {
            int ww2 = w + kw - 1;
            if (ww2 < 0 || ww2 >= WW) continue;
            float xv = xb[hh * WW + ww2];
            acc1 += xv * w1[c * 9 + kh * 3 + kw];
            acc2 += xv * w2[c * 9 + kh * 3 + kw];
        }
    }
    float inv1 = g1[c] * rsqrtf(v1[c] + EPS_F);
    float inv2 = g2[c] * rsqrtf(v2[c] + EPS_F);
    int dst = c * BP + b * NPIX + p;
    g_yq [dst] = acc1 * inv1 + (b1[c] - m1[c] * inv1);
    g_ykv[dst] = acc2 * inv2 + (b2[c] - m2[c] * inv2);
}

// ---------------------------------------------------------------------------
// 2) Generic SGEMM  C[M x BP] = A[M x K] * B[K x BP]
//    Tiles 64x64x16, 256 threads, 4x4 micro-tile per thread.
//    MODE 0: plain store to C (ld = BP).
//    MODE 1: out[(b*CIN + m)*NPIX + p] = acc + bias[m]  (final projection)
// ---------------------------------------------------------------------------
template<int MODE>
__global__ void sgemm64(const float* __restrict__ A, const float* __restrict__ Bm,
                        float* __restrict__ C, int Kdim, const float* __restrict__ bias)
{
    __shared__ float As[16][64];
    __shared__ float Bs[16][64];

    int tid = threadIdx.x;
    int m0 = blockIdx.y * 64;
    int n0 = blockIdx.x * 64;

    int arow = tid >> 2;            // 0..63
    int acol = (tid & 3) * 4;       // 0,4,8,12
    int brow = tid >> 4;            // 0..15
    int bcol = (tid & 15) * 4;
    int ty = tid >> 4;              // 0..15
    int tx = tid & 15;

    const float* Aptr = A + (long)(m0 + arow) * Kdim + acol;
    const float* Bptr = Bm + (long)brow * BP + n0 + bcol;

    float acc[4][4];
#pragma unroll
    for (int i = 0; i < 4; i++)
#pragma unroll
        for (int j = 0; j < 4; j++) acc[i][j] = 0.f;

    for (int k0 = 0; k0 < Kdim; k0 += 16) {
        float4 av = *(const float4*)(Aptr + k0);
        As[acol + 0][arow] = av.x;
        As[acol + 1][arow] = av.y;
        As[acol + 2][arow] = av.z;
        As[acol + 3][arow] = av.w;
        float4 bv = *(const float4*)(Bptr + (long)k0 * BP);
        *(float4*)&Bs[brow][bcol] = bv;
        __syncthreads();
#pragma unroll
        for (int kk = 0; kk < 16; kk++) {
            float a[4], bb[4];
            *(float4*)a  = *(const float4*)&As[kk][ty * 4];
            *(float4*)bb = *(const float4*)&Bs[kk][tx * 4];
#pragma unroll
            for (int i = 0; i < 4; i++)
#pragma unroll
                for (int j = 0; j < 4; j++) acc[i][j] += a[i] * bb[j];
        }
        __syncthreads();
    }

#pragma unroll
    for (int i = 0; i < 4; i++) {
        int m = m0 + ty * 4 + i;
#pragma unroll
        for (int j = 0; j < 4; j++) {
            int n = n0 + tx * 4 + j;
            if (MODE == 0) {
                C[(long)m * BP + n] = acc[i][j];
            } else {
                int b = n / NPIX, p = n % NPIX;
                C[((long)b * CIN + m) * NPIX + p] = acc[i][j] + bias[m];
            }
        }
    }
}

// ---------------------------------------------------------------------------
// 3) diag[bh][n] = SCALE * sum_d q[bh,n,d] * k[bh,n,d]
// ---------------------------------------------------------------------------
__global__ void diag_kernel()
{
    int idx = blockIdx.x * blockDim.x + threadIdx.x;
    if (idx >= NBH * NPIX) return;
    int n  = idx % NPIX;
    int bh = idx / NPIX;
    int b = bh >> 3, h = bh & 7;
    int base = b * NPIX + n;
    float s = 0.f;
#pragma unroll 8
    for (int d = 0; d < DH; d++) {
        float qv = g_q [(h * DH + d) * BP + base];
        float kk = g_kv[(h * DH + d) * BP + base];
        s += qv * kk;
    }
    g_diag[idx] = s * SCALE_F;
}

// ---------------------------------------------------------------------------
// 4) m0_sum = sum of all diag entries (deterministic two-pass)
// ---------------------------------------------------------------------------
__global__ void reduce_diag1()
{
    __shared__ float sm[256];
    float s = 0.f;
    for (int i = blockIdx.x * 256 + threadIdx.x; i < NBH * NPIX; i += 256 * 256)
        s += g_diag[i];
    sm[threadIdx.x] = s;
    __syncthreads();
    for (int st = 128; st > 0; st >>= 1) {
        if (threadIdx.x < st) sm[threadIdx.x] += sm[threadIdx.x + st];
        __syncthreads();
    }
    if (threadIdx.x == 0) g_red[blockIdx.x] = sm[0];
}

__global__ void reduce_diag2()
{
    __shared__ float sm[256];
    sm[threadIdx.x] = g_red[threadIdx.x];
    __syncthreads();
    for (int st = 128; st > 0; st >>= 1) {
        if (threadIdx.x < st) sm[threadIdx.x] += sm[threadIdx.x + st];
        __syncthreads();
    }
    if (threadIdx.x == 0) g_m0[0] = sm[0];
}

// ---------------------------------------------------------------------------
// 5) ktv partials: per (split, bh), C[d][e] += k[n,d]*v[n,e] over the n-range
//    grid (7, 64), 256 threads, 4x4 micro-tile on a 64x64 output
// ---------------------------------------------------------------------------
__global__ void ktv_partial()
{
    __shared__ float Ks[32][65];
    __shared__ float Vs[32][65];

    int split = blockIdx.x;
    int bh = blockIdx.y;
    int b = bh >> 3, h = bh & 7;
    int tid = threadIdx.x;
    int ty = tid >> 4, tx = tid & 15;

    float acc[4][4];
#pragma unroll
    for (int i = 0; i < 4; i++)
#pragma unroll
        for (int j = 0; j < 4; j++) acc[i][j] = 0.f;

    int base = b * NPIX;
    int n_start = split * 448;            // 3136 / 7 = 448

    for (int n0 = n_start; n0 < n_start + 448; n0 += 32) {
#pragma unroll
        for (int l = 0; l < 8; l++) {
            int e  = tid + l * 256;       // 0..2047
            int d  = e >> 5;
            int nn = e & 31;
            Ks[nn][d] = g_kv[(h * DH + d) * BP + base + n0 + nn];
            Vs[nn][d] = g_kv[(INNER + h * DH + d) * BP + base + n0 + nn];
        }
        __syncthreads();
#pragma unroll
        for (int nn = 0; nn < 32; nn++) {
            float a[4], bb[4];
#pragma unroll
            for (int i = 0; i < 4; i++) a[i]  = Ks[nn][ty * 4 + i];
#pragma unroll
            for (int j = 0; j < 4; j++) bb[j] = Vs[nn][tx * 4 + j];
#pragma unroll
            for (int i = 0; i < 4; i++)
#pragma unroll
                for (int j = 0; j < 4; j++) acc[i][j] += a[i] * bb[j];
        }
        __syncthreads();
    }

    float* dst = g_ktvp + ((long)(split * NBH + bh)) * (DH * DH);
#pragma unroll
    for (int i = 0; i < 4; i++)
#pragma unroll
        for (int j = 0; j < 4; j++)
            dst[(ty * 4 + i) * DH + tx * 4 + j] = acc[i][j];
}

__global__ void ktv_reduce()
{
    int idx = blockIdx.x * blockDim.x + threadIdx.x;
    if (idx >= NBH * DH * DH) return;
    float s = 0.f;
#pragma unroll
    for (int sp = 0; sp < 7; sp++)
        s += g_ktvp[(long)sp * (NBH * DH * DH) + idx];
    g_ktv[idx] = s;
}

// ---------------------------------------------------------------------------
// 6) out[bh,n,e] = SCALE * sum_d q[n,d]*ktv[d,e] + (m0 - diag[n]) * v[n,e]
//    grid (98, 64): 32 n per block, 8 e-groups of 8 per thread
// ---------------------------------------------------------------------------
__global__ void att_out_kernel()
{
    __shared__ float ktv_s[DH * DH];
    int bh = blockIdx.y;
    int b = bh >> 3, h = bh & 7;

    for (int i = threadIdx.x; i < DH * DH; i += 256)
        ktv_s[i] = g_ktv[bh * (DH * DH) + i];
    __syncthreads();

    float m0 = g_m0[0];
    int lane_n = threadIdx.x & 31;
    int eg = threadIdx.x >> 5;              // 0..7
    int n = blockIdx.x * 32 + lane_n;
    int base = b * NPIX + n;

    float acc[8];
#pragma unroll
    for (int j = 0; j < 8; j++) acc[j] = 0.f;

#pragma unroll 4
    for (int d = 0; d < DH; d++) {
        float qv = g_q[(h * DH + d) * BP + base];
#pragma unroll
        for (int j = 0; j < 8; j++)
            acc[j] += qv * ktv_s[d * DH + eg * 8 + j];
    }

    float coef = m0 - g_diag[bh * NPIX + n];
#pragma unroll
    for (int j = 0; j < 8; j++) {
        int e = eg * 8 + j;
        float vv = g_kv[(INNER + h * DH + e) * BP + base];
        g_att[(h * DH + e) * BP + base] = SCALE_F * acc[j] + coef * vv;
    }
}

// ---------------------------------------------------------------------------
// Launch
// ---------------------------------------------------------------------------
extern "C" void kernel_launch(void* const* d_in, const int* in_sizes, int n_in,
                              void* d_out, int out_size)
{
    const float* x       = (const float*)d_in[0];
    const float* wq_dw   = (const float*)d_in[1];
    const float* wq_g    = (const float*)d_in[2];
    const float* wq_b    = (const float*)d_in[3];
    const float* wq_m    = (const float*)d_in[4];
    const float* wq_v    = (const float*)d_in[5];
    const float* wq_pw   = (const float*)d_in[6];
    const float* wkv_dw  = (const float*)d_in[7];
    const float* wkv_g   = (const float*)d_in[8];
    const float* wkv_b   = (const float*)d_in[9];
    const float* wkv_m   = (const float*)d_in[10];
    const float* wkv_v   = (const float*)d_in[11];
    const float* wkv_pw  = (const float*)d_in[12];
    const float* wo      = (const float*)d_in[13];
    const float* bo      = (const float*)d_in[14];
    float* out = (float*)d_out;

    float *p_yq, *p_ykv, *p_q, *p_kv, *p_att;
    cudaGetSymbolAddress((void**)&p_yq,  g_yq);
    cudaGetSymbolAddress((void**)&p_ykv, g_ykv);
    cudaGetSymbolAddress((void**)&p_q,   g_q);
    cudaGetSymbolAddress((void**)&p_kv,  g_kv);
    cudaGetSymbolAddress((void**)&p_att, g_att);

    // 1) depthwise conv + BN, both paths
    dwconv_bn_kernel<<<(BATCH * CIN * NPIX) / 256, 256>>>(
        x, wq_dw, wq_g, wq_b, wq_m, wq_v,
           wkv_dw, wkv_g, wkv_b, wkv_m, wkv_v);

    // 2) pointwise projections
    sgemm64<0><<<dim3(BP / 64, INNER / 64), 256>>>(wq_pw,  p_yq,  p_q,  CIN, nullptr);
    sgemm64<0><<<dim3(BP / 64, KVOUT / 64), 256>>>(wkv_pw, p_ykv, p_kv, CIN, nullptr);

    // 3) attention middle
    diag_kernel<<<(NBH * NPIX) / 256, 256>>>();
    reduce_diag1<<<256, 256>>>();
    reduce_diag2<<<1, 256>>>();
    ktv_partial<<<dim3(7, NBH), 256>>>();
    ktv_reduce<<<(NBH * DH * DH) / 256, 256>>>();
    att_out_kernel<<<dim3(NPIX / 32, NBH), 256>>>();

    // 4) output projection (+bias, NCHW scatter)
    sgemm64<1><<<dim3(BP / 64, CIN / 64), 256>>>(wo, p_att, out, INNER, bo);
}

// round 3
// speedup vs baseline: 2.4451x; 2.4451x over previous
#include <cuda_runtime.h>
#include <cstdint>

// Problem constants
#define BATCH   8
#define CIN     384
#define NPIX    3136           // 56*56
#define WWID    56
#define BP      25088          // BATCH*NPIX
#define INNER   512
#define KVOUT   1024
#define HEADS   8
#define DH      64
#define NBH     64
#define SCALE_F 0.125f
#define EPS_F   1e-5f

// ---------------------------------------------------------------------------
// Scratch (device globals)
// ---------------------------------------------------------------------------
__device__ __align__(16) float g_yq [(size_t)BP * CIN];    // dwconv out, q path  [n][c] (tf32-rounded)
__device__ __align__(16) float g_ykv[(size_t)BP * CIN];    // dwconv out, kv path [n][c] (tf32-rounded)
__device__ __align__(16) float g_q  [(size_t)INNER * BP];  // q   [m][n]
__device__ __align__(16) float g_kv [(size_t)KVOUT * BP];  // k|v [m][n]
__device__ __align__(16) float g_att[(size_t)BP * INNER];  // attention out [n][o] (tf32-rounded)
__device__ __align__(16) float g_wq_c [INNER * CIN];       // tf32-rounded weights
__device__ __align__(16) float g_wkv_c[KVOUT * CIN];
__device__ __align__(16) float g_wo_c [CIN * INNER];
__device__ float g_diag[NBH * NPIX];
__device__ float g_ktvp[7 * NBH * DH * DH];
__device__ float g_ktv [NBH * DH * DH];
__device__ float g_red[256];
__device__ float g_m0[1];

// ---------------------------------------------------------------------------
// Helpers
// ---------------------------------------------------------------------------
__device__ __forceinline__ float tf32r(float x) {
    uint32_t r;
    asm("cvt.rna.tf32.f32 %0, %1;" : "=r"(r) : "f"(x));
    return __uint_as_float(r);
}
__device__ __forceinline__ uint32_t smem_u32(const void* p) {
    uint32_t a;
    asm("{ .reg .u64 t; cvta.to.shared.u64 t, %1; cvt.u32.u64 %0, t; }" : "=r"(a) : "l"(p));
    return a;
}
__device__ __forceinline__ void cp_async16(uint32_t dst, const void* src) {
    asm volatile("cp.async.cg.shared.global [%0], [%1], 16;" :: "r"(dst), "l"(src));
}
#define CP_COMMIT() asm volatile("cp.async.commit_group;" ::: "memory")
#define CP_WAIT(N)  asm volatile("cp.async.wait_group %0;" :: "n"(N) : "memory")

__device__ __forceinline__ void mma_tf32(float* c, const uint32_t* a, const uint32_t* b) {
    asm volatile(
        "mma.sync.aligned.m16n8k8.row.col.f32.tf32.tf32.f32 "
        "{%0,%1,%2,%3}, {%4,%5,%6,%7}, {%8,%9}, {%0,%1,%2,%3};"
        : "+f"(c[0]), "+f"(c[1]), "+f"(c[2]), "+f"(c[3])
        : "r"(a[0]), "r"(a[1]), "r"(a[2]), "r"(a[3]), "r"(b[0]), "r"(b[1]));
}

// ---------------------------------------------------------------------------
// 0) Weight conversion (fp32 -> tf32-rounded fp32)
// ---------------------------------------------------------------------------
__global__ void cvt_tf32_kernel(const float* __restrict__ src, float* __restrict__ dst, int n)
{
    int i = blockIdx.x * 256 + threadIdx.x;
    if (i < n) dst[i] = tf32r(src[i]);
}

// ---------------------------------------------------------------------------
// 1) Depthwise 3x3 conv + BN, output TRANSPOSED to [n][c], tf32-rounded
// ---------------------------------------------------------------------------
__global__ void dwconv_bn_kernel(
    const float* __restrict__ x,
    const float* __restrict__ w1, const float* __restrict__ g1, const float* __restrict__ b1,
    const float* __restrict__ m1, const float* __restrict__ v1,
    const float* __restrict__ w2, const float* __restrict__ g2, const float* __restrict__ b2,
    const float* __restrict__ m2, const float* __restrict__ v2)
{
    __shared__ float s1[32][65];
    __shared__ float s2[32][65];
    int b  = blockIdx.z;
    int ct = blockIdx.y;     // 12 channel tiles of 32
    int pt = blockIdx.x;     // 49 pixel tiles of 64
    int tid = threadIdx.x;
    int p_loc = tid & 63;
    int c_sub = tid >> 6;
    int p = pt * 64 + p_loc;
    int h = p / WWID, w = p % WWID;

#pragma unroll
    for (int i = 0; i < 8; i++) {
        int c_loc = i * 4 + c_sub;
        int c = ct * 32 + c_loc;
        const float* xb = x + ((size_t)(b * CIN + c)) * NPIX;
        float acc1 = 0.f, acc2 = 0.f;
#pragma unroll
        for (int kh = 0; kh < 3; kh++) {
            int hh = h + kh - 1;
            if (hh < 0 || hh >= WWID) continue;
#pragma unroll
            for (int kw = 0; kw < 3; kw++) {
                int ww2 = w + kw - 1;
                if (ww2 < 0 || ww2 >= WWID) continue;
                float xv = xb[hh * WWID + ww2];
                acc1 += xv * w1[c * 9 + kh * 3 + kw];
                acc2 += xv * w2[c * 9 + kh * 3 + kw];
            }
        }
        float inv1 = g1[c] * rsqrtf(v1[c] + EPS_F);
        float inv2 = g2[c] * rsqrtf(v2[c] + EPS_F);
        s1[c_loc][p_loc] = acc1 * inv1 + (b1[c] - m1[c] * inv1);
        s2[c_loc][p_loc] = acc2 * inv2 + (b2[c] - m2[c] * inv2);
    }
    __syncthreads();

#pragma unroll
    for (int i = 0; i < 2; i++) {
        int idx = tid + i * 256;
        int pp  = idx >> 3;
        int cq  = idx & 7;
        size_t base = ((size_t)(b * NPIX + pt * 64 + pp)) * CIN + ct * 32 + cq * 4;
        float4 v1o = make_float4(tf32r(s1[cq*4+0][pp]), tf32r(s1[cq*4+1][pp]),
                                 tf32r(s1[cq*4+2][pp]), tf32r(s1[cq*4+3][pp]));
        float4 v2o = make_float4(tf32r(s2[cq*4+0][pp]), tf32r(s2[cq*4+1][pp]),
                                 tf32r(s2[cq*4+2][pp]), tf32r(s2[cq*4+3][pp]));
        *(float4*)(g_yq  + base) = v1o;
        *(float4*)(g_ykv + base) = v2o;
    }
}

// ---------------------------------------------------------------------------
// 2) tf32 mma.sync GEMM: C[m][n] = sum_k A[m][k] * B[n][k]
//    A: [M][Kd] row-major (tf32-rounded weights)
//    B: [BP][Kd] row-major (tf32-rounded activations)
//    CTA 128x128, K-tile 32, cp.async double buffer, 8 warps of 64x32.
//    MODE 0: C[m*BP + n].  MODE 1: NCHW scatter + bias.
// ---------------------------------------------------------------------------
#define KTILE   32
#define SROW    36                         // floats per SMEM row (stride)
#define TILE_F  (128 * SROW)               // floats per operand tile
#define SMEM_GEMM_BYTES (2 * 2 * TILE_F * 4)

template<int MODE>
__global__ void __launch_bounds__(256, 2) gemm_tf32(
    const float* __restrict__ A, const float* __restrict__ Bm,
    float* __restrict__ C, int Kd, const float* __restrict__ bias)
{
    extern __shared__ float smem[];
    int tid = threadIdx.x;
    int wid = tid >> 5;
    int lane = tid & 31;
    int grp = lane >> 2;          // 0..7
    int qid = lane & 3;           // 0..3
    int warp_m = wid & 1;         // 0..1
    int warp_n = wid >> 1;        // 0..3

    int n0 = blockIdx.x * 128;
    int m0 = blockIdx.y * 128;
    int KT = Kd / KTILE;

    uint32_t smem_b = smem_u32(smem);

    // tile loader: 128 rows x 8 float4 per operand, 256 threads -> 4 iters each
    auto load_tile = [&](int kt, int buf) {
        int k0 = kt * KTILE;
        uint32_t dA = smem_b + (uint32_t)buf * (2 * TILE_F * 4);
        uint32_t dB = dA + TILE_F * 4;
#pragma unroll
        for (int i = 0; i < 4; i++) {
            int idx = tid + i * 256;
            int row = idx >> 3, q = idx & 7;
            cp_async16(dA + (uint32_t)(row * SROW + q * 4) * 4,
                       A + (size_t)(m0 + row) * Kd + k0 + q * 4);
        }
#pragma unroll
        for (int i = 0; i < 4; i++) {
            int idx = tid + i * 256;
            int row = idx >> 3, q = idx & 7;
            cp_async16(dB + (uint32_t)(row * SROW + q * 4) * 4,
                       Bm + (size_t)(n0 + row) * Kd + k0 + q * 4);
        }
    };

    float acc[4][4][4];
#pragma unroll
    for (int mt = 0; mt < 4; mt++)
#pragma unroll
        for (int nt = 0; nt < 4; nt++)
#pragma unroll
            for (int r = 0; r < 4; r++) acc[mt][nt][r] = 0.f;

    load_tile(0, 0);
    CP_COMMIT();

    int a_row0 = warp_m * 64 + grp;
    int b_row0 = warp_n * 32 + grp;

    for (int kt = 0; kt < KT; kt++) {
        int buf = kt & 1;
        if (kt + 1 < KT) {
            load_tile(kt + 1, buf ^ 1);
            CP_COMMIT();
            CP_WAIT(1);
        } else {
            CP_WAIT(0);
        }
        __syncthreads();

        const float* As = smem + buf * (2 * TILE_F);
        const float* Bs = As + TILE_F;

#pragma unroll
        for (int ks = 0; ks < 4; ks++) {
            int k0 = ks * 8 + qid;
            uint32_t afr[4][4], bfr[4][2];
#pragma unroll
            for (int mt = 0; mt < 4; mt++) {
                const float* base = As + (a_row0 + mt * 16) * SROW + k0;
                afr[mt][0] = __float_as_uint(base[0]);
                afr[mt][1] = __float_as_uint(base[8 * SROW]);
                afr[mt][2] = __float_as_uint(base[4]);
                afr[mt][3] = __float_as_uint(base[8 * SROW + 4]);
            }
#pragma unroll
            for (int nt = 0; nt < 4; nt++) {
                const float* base = Bs + (b_row0 + nt * 8) * SROW + k0;
                bfr[nt][0] = __float_as_uint(base[0]);
                bfr[nt][1] = __float_as_uint(base[4]);
            }
#pragma unroll
            for (int mt = 0; mt < 4; mt++)
#pragma unroll
                for (int nt = 0; nt < 4; nt++)
                    mma_tf32(acc[mt][nt], afr[mt], bfr[nt]);
        }
        __syncthreads();
    }

    // Epilogue
#pragma unroll
    for (int mt = 0; mt < 4; mt++) {
        int r0 = m0 + warp_m * 64 + mt * 16 + grp;
        int r1 = r0 + 8;
        float bs0 = (MODE == 1) ? bias[r0] : 0.f;
        float bs1 = (MODE == 1) ? bias[r1] : 0.f;
#pragma unroll
        for (int nt = 0; nt < 4; nt++) {
            int n = n0 + warp_n * 32 + nt * 8 + qid * 2;
            float* a4 = acc[mt][nt];
            if (MODE == 0) {
                *(float2*)(C + (size_t)r0 * BP + n) = make_float2(a4[0], a4[1]);
                *(float2*)(C + (size_t)r1 * BP + n) = make_float2(a4[2], a4[3]);
            } else {
                int bb = n / NPIX, p = n - bb * NPIX;   // n even, NPIX even -> no split
                *(float2*)(C + ((size_t)bb * CIN + r0) * NPIX + p) =
                    make_float2(a4[0] + bs0, a4[1] + bs0);
                *(float2*)(C + ((size_t)bb * CIN + r1) * NPIX + p) =
                    make_float2(a4[2] + bs1, a4[3] + bs1);
            }
        }
    }
}

// ---------------------------------------------------------------------------
// 3) diag[bh][n] = SCALE * sum_d q[bh,n,d] * k[bh,n,d]
// ---------------------------------------------------------------------------
__global__ void diag_kernel()
{
    int idx = blockIdx.x * blockDim.x + threadIdx.x;
    if (idx >= NBH * NPIX) return;
    int n  = idx % NPIX;
    int bh = idx / NPIX;
    int b = bh >> 3, h = bh & 7;
    int base = b * NPIX + n;
    float s = 0.f;
#pragma unroll 8
    for (int d = 0; d < DH; d++) {
        float qv = g_q [(size_t)(h * DH + d) * BP + base];
        float kk = g_kv[(size_t)(h * DH + d) * BP + base];
        s += qv * kk;
    }
    g_diag[idx] = s * SCALE_F;
}

__global__ void reduce_diag1()
{
    __shared__ float sm[256];
    float s = 0.f;
    for (int i = blockIdx.x * 256 + threadIdx.x; i < NBH * NPIX; i += 256 * 256)
        s += g_diag[i];
    sm[threadIdx.x] = s;
    __syncthreads();
    for (int st = 128; st > 0; st >>= 1) {
        if (threadIdx.x < st) sm[threadIdx.x] += sm[threadIdx.x + st];
        __syncthreads();
    }
    if (threadIdx.x == 0) g_red[blockIdx.x] = sm[0];
}
__global__ void reduce_diag2()
{
    __shared__ float sm[256];
    sm[threadIdx.x] = g_red[threadIdx.x];
    __syncthreads();
    for (int st = 128; st > 0; st >>= 1) {
        if (threadIdx.x < st) sm[threadIdx.x] += sm[threadIdx.x + st];
        __syncthreads();
    }
    if (threadIdx.x == 0) g_m0[0] = sm[0];
}

// ---------------------------------------------------------------------------
// 5) ktv partials + reduce
// ---------------------------------------------------------------------------
__global__ void ktv_partial()
{
    __shared__ float Ks[32][65];
    __shared__ float Vs[32][65];
    int split = blockIdx.x;
    int bh = blockIdx.y;
    int b = bh >> 3, h = bh & 7;
    int tid = threadIdx.x;
    int ty = tid >> 4, tx = tid & 15;

    float acc[4][4];
#pragma unroll
    for (int i = 0; i < 4; i++)
#pragma unroll
        for (int j = 0; j < 4; j++) acc[i][j] = 0.f;

    int base = b * NPIX;
    int n_start = split * 448;

    for (int n0 = n_start; n0 < n_start + 448; n0 += 32) {
#pragma unroll
        for (int l = 0; l < 8; l++) {
            int e  = tid + l * 256;
            int d  = e >> 5;
            int nn = e & 31;
            Ks[nn][d] = g_kv[(size_t)(h * DH + d) * BP + base + n0 + nn];
            Vs[nn][d] = g_kv[(size_t)(INNER + h * DH + d) * BP + base + n0 + nn];
        }
        __syncthreads();
#pragma unroll
        for (int nn = 0; nn < 32; nn++) {
            float a[4], bb[4];
#pragma unroll
            for (int i = 0; i < 4; i++) a[i]  = Ks[nn][ty * 4 + i];
#pragma unroll
            for (int j = 0; j < 4; j++) bb[j] = Vs[nn][tx * 4 + j];
#pragma unroll
            for (int i = 0; i < 4; i++)
#pragma unroll
                for (int j = 0; j < 4; j++) acc[i][j] += a[i] * bb[j];
        }
        __syncthreads();
    }
    float* dst = g_ktvp + ((size_t)(split * NBH + bh)) * (DH * DH);
#pragma unroll
    for (int i = 0; i < 4; i++)
#pragma unroll
        for (int j = 0; j < 4; j++)
            dst[(ty * 4 + i) * DH + tx * 4 + j] = acc[i][j];
}

__global__ void ktv_reduce()
{
    int idx = blockIdx.x * blockDim.x + threadIdx.x;
    if (idx >= NBH * DH * DH) return;
    float s = 0.f;
#pragma unroll
    for (int sp = 0; sp < 7; sp++)
        s += g_ktvp[(size_t)sp * (NBH * DH * DH) + idx];
    g_ktv[idx] = s;
}

// ---------------------------------------------------------------------------
// 6) att_out: g_att[n][h*64+e] = SCALE*sum_d q[n,d]*ktv[d,e] + (m0-diag[n])*v[n,e]
//    tf32-rounded, layout [n][512] for the final tensor-core GEMM.
// ---------------------------------------------------------------------------
__global__ void att_out_kernel()
{
    __shared__ float ktv_s[DH * DH];
    int bh = blockIdx.y;
    int b = bh >> 3, h = bh & 7;

    for (int i = threadIdx.x; i < DH * DH; i += 256)
        ktv_s[i] = g_ktv[bh * (DH * DH) + i];
    __syncthreads();

    float m0 = g_m0[0];
    int lane_n = threadIdx.x & 31;           // 32 consecutive n per warp
    int eg = threadIdx.x >> 5;               // 0..7
    int n = blockIdx.x * 32 + lane_n;
    int base = b * NPIX + n;

    float acc[8];
#pragma unroll
    for (int j = 0; j < 8; j++) acc[j] = 0.f;

#pragma unroll 4
    for (int d = 0; d < DH; d++) {
        float qv = g_q[(size_t)(h * DH + d) * BP + base];
#pragma unroll
        for (int j = 0; j < 8; j++)
            acc[j] += qv * ktv_s[d * DH + eg * 8 + j];
    }

    float coef = m0 - g_diag[bh * NPIX + n];
    float outv[8];
#pragma unroll
    for (int j = 0; j < 8; j++) {
        int e = eg * 8 + j;
        float vv = g_kv[(size_t)(INNER + h * DH + e) * BP + base];
        outv[j] = tf32r(SCALE_F * acc[j] + coef * vv);
    }
    float* dst = g_att + (size_t)base * INNER + h * DH + eg * 8;
    *(float4*)(dst)     = make_float4(outv[0], outv[1], outv[2], outv[3]);
    *(float4*)(dst + 4) = make_float4(outv[4], outv[5], outv[6], outv[7]);
}

// ---------------------------------------------------------------------------
// Launch
// ---------------------------------------------------------------------------
extern "C" void kernel_launch(void* const* d_in, const int* in_sizes, int n_in,
                              void* d_out, int out_size)
{
    const float* x       = (const float*)d_in[0];
    const float* wq_dw   = (const float*)d_in[1];
    const float* wq_g    = (const float*)d_in[2];
    const float* wq_b    = (const float*)d_in[3];
    const float* wq_m    = (const float*)d_in[4];
    const float* wq_v    = (const float*)d_in[5];
    const float* wq_pw   = (const float*)d_in[6];
    const float* wkv_dw  = (const float*)d_in[7];
    const float* wkv_g   = (const float*)d_in[8];
    const float* wkv_b   = (const float*)d_in[9];
    const float* wkv_m   = (const float*)d_in[10];
    const float* wkv_v   = (const float*)d_in[11];
    const float* wkv_pw  = (const float*)d_in[12];
    const float* wo      = (const float*)d_in[13];
    const float* bo      = (const float*)d_in[14];
    float* out = (float*)d_out;

    float *p_yq, *p_ykv, *p_q, *p_kv, *p_att, *p_wq, *p_wkv, *p_wo;
    cudaGetSymbolAddress((void**)&p_yq,  g_yq);
    cudaGetSymbolAddress((void**)&p_ykv, g_ykv);
    cudaGetSymbolAddress((void**)&p_q,   g_q);
    cudaGetSymbolAddress((void**)&p_kv,  g_kv);
    cudaGetSymbolAddress((void**)&p_att, g_att);
    cudaGetSymbolAddress((void**)&p_wq,  g_wq_c);
    cudaGetSymbolAddress((void**)&p_wkv, g_wkv_c);
    cudaGetSymbolAddress((void**)&p_wo,  g_wo_c);

    cudaFuncSetAttribute(gemm_tf32<0>, cudaFuncAttributeMaxDynamicSharedMemorySize, SMEM_GEMM_BYTES);
    cudaFuncSetAttribute(gemm_tf32<1>, cudaFuncAttributeMaxDynamicSharedMemorySize, SMEM_GEMM_BYTES);

    // 0) weight conversion to tf32
    cvt_tf32_kernel<<<(INNER * CIN + 255) / 256, 256>>>(wq_pw,  p_wq,  INNER * CIN);
    cvt_tf32_kernel<<<(KVOUT * CIN + 255) / 256, 256>>>(wkv_pw, p_wkv, KVOUT * CIN);
    cvt_tf32_kernel<<<(CIN * INNER + 255) / 256, 256>>>(wo,     p_wo,  CIN * INNER);

    // 1) depthwise conv + BN (transposed output [n][c], tf32-rounded)
    dwconv_bn_kernel<<<dim3(49, 12, 8), 256>>>(
        x, wq_dw, wq_g, wq_b, wq_m, wq_v,
           wkv_dw, wkv_g, wkv_b, wkv_m, wkv_v);

    // 2) pointwise projections on tensor cores (tf32 mma.sync)
    gemm_tf32<0><<<dim3(196, 4), 256, SMEM_GEMM_BYTES>>>(p_wq,  p_yq,  p_q,  CIN, nullptr);
    gemm_tf32<0><<<dim3(196, 8), 256, SMEM_GEMM_BYTES>>>(p_wkv, p_ykv, p_kv, CIN, nullptr);

    // 3) attention middle
    diag_kernel<<<(NBH * NPIX) / 256, 256>>>();
    reduce_diag1<<<256, 256>>>();
    reduce_diag2<<<1, 256>>>();
    ktv_partial<<<dim3(7, NBH), 256>>>();
    ktv_reduce<<<(NBH * DH * DH) / 256, 256>>>();
    att_out_kernel<<<dim3(NPIX / 32, NBH), 256>>>();

    // 4) output projection (+bias, NCHW scatter) on tensor cores
    gemm_tf32<1><<<dim3(196, 3), 256, SMEM_GEMM_BYTES>>>(p_wo, p_att, out, INNER, bo);
}